// round 11
// baseline (speedup 1.0000x reference)
#include <cuda_runtime.h>

#define N_NODES 50000
#define N_EDGES 800000
#define N_GRAPHS 50
#define IN_FEATS 128
#define H1F 64
#define O2F 32
#define CAP 96     // max in-degree capacity (Poisson(16): P(deg>=96) ~ 0)

// ---------------- scratch (device globals; no allocation allowed) ----------
__device__ float g_z1[N_NODES * H1F];
__device__ float g_h1[N_NODES * H1F];
__device__ float g_z2[N_NODES * O2F];
__device__ float g_el[N_NODES];
__device__ float g_er[N_NODES];
__device__ int   g_cur[N_NODES];          // per-node degree counter; invariant:
                                          // zero at kernel_launch entry
__device__ int   g_esrc[N_NODES * CAP];   // fixed-capacity adjacency rows
__device__ float g_cnt[N_GRAPHS];

// ---------------- build fixed-capacity adjacency (single kernel!) -----------
// g_cur is zero on entry (globals start zeroed; agg2 restores the invariant).
// Block 0 additionally zeroes the pooled output and counts.
__global__ void scatter_kernel(const int* __restrict__ src,
                               const int* __restrict__ dst,
                               float* __restrict__ out) {
    if (blockIdx.x == 0) {
        for (int t = threadIdx.x; t < N_GRAPHS * O2F; t += blockDim.x)
            out[t] = 0.0f;
        for (int t = threadIdx.x; t < N_GRAPHS; t += blockDim.x)
            g_cnt[t] = 0.0f;
    }
    int i = blockIdx.x * blockDim.x + threadIdx.x;
    if (i >= N_EDGES / 2) return;
    int j = i + N_EDGES / 2;
    int d0 = dst[i], d1 = dst[j];
    int s0 = src[i], s1 = src[j];
    int p0 = atomicAdd(&g_cur[d0], 1);
    int p1 = atomicAdd(&g_cur[d1], 1);
    if (p0 < CAP) g_esrc[d0 * CAP + p0] = s0;
    if (p1 < CAP) g_esrc[d1 * CAP + p1] = s1;
}

// ---------------- node GEMM + attention logits (8x4 register tiling) --------
template <int IN, int OUT, int NPB>
__global__ void gemm_attn_kernel(const float* __restrict__ H,
                                 const float* __restrict__ W,
                                 const float* __restrict__ al,
                                 const float* __restrict__ ar,
                                 float* __restrict__ Z,
                                 float* __restrict__ EL,
                                 float* __restrict__ ER) {
    constexpr int CG = OUT / 4;
    constexpr int NG = NPB / 8;
    constexpr int NT = CG * NG;        // 256
    constexpr int KC = 32;
    constexpr int NKC = IN / KC;
    constexpr int KQ = KC / 4;
    constexpr int PITCH = NPB + 4;

    __shared__ float sx[KC * PITCH];
    __shared__ float sW[KC * OUT];

    int tid = threadIdx.x;
    int base = blockIdx.x * NPB;
    int ng = tid / CG, cg = tid % CG;
    int nn = ng * 8;

    float4 acc[8];
#pragma unroll
    for (int n = 0; n < 8; n++) acc[n] = make_float4(0.f, 0.f, 0.f, 0.f);

    for (int kc = 0; kc < NKC; kc++) {
        __syncthreads();
        for (int t = tid; t < KC * OUT / 4; t += NT)
            ((float4*)sW)[t] = ((const float4*)W)[kc * (KC * OUT / 4) + t];
        for (int t = tid; t < NPB * KQ; t += NT) {
            int node = t / KQ, kq = t % KQ;
            float4 v = make_float4(0.f, 0.f, 0.f, 0.f);
            if (base + node < N_NODES)
                v = ((const float4*)(H + (size_t)(base + node) * IN))[kc * KQ + kq];
            sx[(kq * 4 + 0) * PITCH + node] = v.x;
            sx[(kq * 4 + 1) * PITCH + node] = v.y;
            sx[(kq * 4 + 2) * PITCH + node] = v.z;
            sx[(kq * 4 + 3) * PITCH + node] = v.w;
        }
        __syncthreads();

#pragma unroll 8
        for (int k = 0; k < KC; k++) {
            float4 xa = *(const float4*)(sx + k * PITCH + nn);
            float4 xb = *(const float4*)(sx + k * PITCH + nn + 4);
            float4 w  = *(const float4*)(sW + k * OUT + cg * 4);
            float xs[8] = {xa.x, xa.y, xa.z, xa.w, xb.x, xb.y, xb.z, xb.w};
#pragma unroll
            for (int n = 0; n < 8; n++) {
                acc[n].x += xs[n] * w.x;
                acc[n].y += xs[n] * w.y;
                acc[n].z += xs[n] * w.z;
                acc[n].w += xs[n] * w.w;
            }
        }
    }

    float4 av = ((const float4*)al)[cg];
    float4 rv = ((const float4*)ar)[cg];
#pragma unroll
    for (int n = 0; n < 8; n++) {
        float l = acc[n].x * av.x + acc[n].y * av.y +
                  acc[n].z * av.z + acc[n].w * av.w;
        float r = acc[n].x * rv.x + acc[n].y * rv.y +
                  acc[n].z * rv.z + acc[n].w * rv.w;
#pragma unroll
        for (int off = CG / 2; off > 0; off >>= 1) {
            l += __shfl_xor_sync(0xffffffffu, l, off);
            r += __shfl_xor_sync(0xffffffffu, r, off);
        }
        int node = base + nn + n;
        if (node < N_NODES) {
            ((float4*)(Z + (size_t)node * OUT))[cg] = acc[n];
            if (cg == 0) { EL[node] = l; ER[node] = r; }
        }
    }
}

// ---------------- fused softmax + aggregation (max-free), warp per node -----
// RESET: the POOL (last) variant resets g_cur[wid] = 0 for the next replay.
template <int OUT, bool POOL>
__global__ void node_agg_kernel(const float* __restrict__ Z,
                                const float* __restrict__ b,
                                float* __restrict__ Hout,
                                const int* __restrict__ gid,
                                float* __restrict__ out) {
    constexpr int LPE = OUT / 4;
    constexpr int EPI = 32 / LPE;
    int wid  = (blockIdx.x * blockDim.x + threadIdx.x) >> 5;
    int lane = threadIdx.x & 31;
    if (wid >= N_NODES) return;

    int deg = min(g_cur[wid], CAP);
    const int* row = g_esrc + (size_t)wid * CAP;
    float erd = g_er[wid];
    int sub = lane / LPE;
    int fl  = lane % LPE;

    float s_lane = 0.f;
    float4 acc = make_float4(0.f, 0.f, 0.f, 0.f);

    for (int base = 0; base < deg; base += 32) {
        int t = base + lane;
        bool valid = t < deg;
        int sN = valid ? row[t] : 0;
        float a = 0.f;
        if (valid) {
            float v = g_el[sN] + erd;
            v = (v > 0.f) ? v : 0.2f * v;
            a = __expf(v);
        }
        s_lane += a;

        int cnt = min(32, deg - base);
        for (int j = 0; j < cnt; j += EPI) {
            int ei = j + sub;
            float alpha = __shfl_sync(0xffffffffu, a, ei);
            int   sn    = __shfl_sync(0xffffffffu, sN, ei);
            float4 zv = ((const float4*)(Z + (size_t)sn * OUT))[fl];
            acc.x += alpha * zv.x;
            acc.y += alpha * zv.y;
            acc.z += alpha * zv.z;
            acc.w += alpha * zv.w;
        }
    }

    float s = s_lane;
#pragma unroll
    for (int off = 16; off > 0; off >>= 1)
        s += __shfl_xor_sync(0xffffffffu, s, off);
#pragma unroll
    for (int off = 16; off >= LPE; off >>= 1) {
        acc.x += __shfl_xor_sync(0xffffffffu, acc.x, off);
        acc.y += __shfl_xor_sync(0xffffffffu, acc.y, off);
        acc.z += __shfl_xor_sync(0xffffffffu, acc.z, off);
        acc.w += __shfl_xor_sync(0xffffffffu, acc.w, off);
    }

    if (POOL && lane == 0) g_cur[wid] = 0;   // restore invariant for replay

    if (lane < LPE) {
        float inv_s = (deg > 0) ? 1.f / s : 0.f;
        float4 bq = ((const float4*)b)[fl];
        float4 h;
        h.x = acc.x * inv_s + bq.x;
        h.y = acc.y * inv_s + bq.y;
        h.z = acc.z * inv_s + bq.z;
        h.w = acc.w * inv_s + bq.w;
        h.x = (h.x > 0.f) ? h.x : 0.01f * h.x;
        h.y = (h.y > 0.f) ? h.y : 0.01f * h.y;
        h.z = (h.z > 0.f) ? h.z : 0.01f * h.z;
        h.w = (h.w > 0.f) ? h.w : 0.01f * h.w;
        if (POOL) {
            int g = gid[wid];
            atomicAdd(((float4*)(out + g * O2F)) + fl, h);
            if (lane == 0) atomicAdd(&g_cnt[g], 1.f);
        } else {
            ((float4*)(Hout + (size_t)wid * OUT))[fl] = h;
        }
    }
}

// ---------------- final divide ----------------------------------------------
__global__ void pool_div_kernel(float* __restrict__ out) {
    int i = blockIdx.x * blockDim.x + threadIdx.x;
    if (i >= N_GRAPHS * O2F) return;
    float c = g_cnt[i / O2F];
    out[i] /= fmaxf(c, 1.0f);
}

// ---------------- stream/event singletons (created once, outside capture) ---
static cudaStream_t g_s1;
static cudaEvent_t  g_evFork, g_evJoin;
static int g_res_init = []() {
    cudaStreamCreateWithFlags(&g_s1, cudaStreamNonBlocking);
    cudaEventCreateWithFlags(&g_evFork, cudaEventDisableTiming);
    cudaEventCreateWithFlags(&g_evJoin, cudaEventDisableTiming);
    return 0;
}();

// ---------------- host launch -------------------------------------------------
extern "C" void kernel_launch(void* const* d_in, const int* in_sizes, int n_in,
                              void* d_out, int out_size) {
    const float* x   = (const float*)d_in[0];
    const int*   src = (const int*)d_in[1];
    const int*   dst = (const int*)d_in[2];
    const int*   gid = (const int*)d_in[3];
    const float* W1  = (const float*)d_in[4];
    const float* al1 = (const float*)d_in[5];
    const float* ar1 = (const float*)d_in[6];
    const float* b1  = (const float*)d_in[7];
    const float* W2  = (const float*)d_in[8];
    const float* al2 = (const float*)d_in[9];
    const float* ar2 = (const float*)d_in[10];
    const float* b2  = (const float*)d_in[11];
    float* out = (float*)d_out;

    float *z1, *h1, *z2, *el, *er;
    cudaGetSymbolAddress((void**)&z1, g_z1);
    cudaGetSymbolAddress((void**)&h1, g_h1);
    cudaGetSymbolAddress((void**)&z2, g_z2);
    cudaGetSymbolAddress((void**)&el, g_el);
    cudaGetSymbolAddress((void**)&er, g_er);

    const int TB = 256;
    const int edge2_blocks = (N_EDGES / 2 + TB - 1) / TB;
    const int agg_blocks   = (N_NODES * 32) / TB;        // 6250

    // fork: adjacency build on side stream, gemm1 on main stream
    cudaEventRecord(g_evFork, 0);
    cudaStreamWaitEvent(g_s1, g_evFork, 0);

    scatter_kernel<<<edge2_blocks, TB, 0, g_s1>>>(src, dst, out);
    cudaEventRecord(g_evJoin, g_s1);

    gemm_attn_kernel<IN_FEATS, H1F, 128>
        <<<(N_NODES + 127) / 128, 256>>>(x, W1, al1, ar1, z1, el, er);

    cudaStreamWaitEvent(0, g_evJoin, 0);

    node_agg_kernel<H1F, false><<<agg_blocks, TB>>>(z1, b1, h1, gid, out);

    gemm_attn_kernel<H1F, O2F, 256>
        <<<(N_NODES + 255) / 256, 256>>>(h1, W2, al2, ar2, z2, el, er);

    node_agg_kernel<O2F, true><<<agg_blocks, TB>>>(z2, b2, nullptr, gid, out);

    pool_div_kernel<<<(N_GRAPHS * O2F + TB - 1) / TB, TB>>>(out);
}

// round 12
// speedup vs baseline: 1.0155x; 1.0155x over previous
#include <cuda_runtime.h>

#define N_NODES 50000
#define N_EDGES 800000
#define N_GRAPHS 50
#define IN_FEATS 128
#define H1F 64
#define O2F 32
#define CAP 96     // max in-degree capacity (Poisson(16): P(deg>=96) ~ 0)

// ---------------- scratch (device globals; no allocation allowed) ----------
__device__ float g_z1[N_NODES * H1F];
__device__ float g_h1[N_NODES * H1F];
__device__ float g_z2[N_NODES * O2F];
__device__ float g_el[N_NODES];
__device__ float g_er[N_NODES];
__device__ int   g_cur[N_NODES];          // per-node degree counter; invariant:
                                          // zero at kernel_launch entry
__device__ int   g_esrc[N_NODES * CAP];   // fixed-capacity adjacency rows
__device__ float g_cnt[N_GRAPHS];

// ---------------- build fixed-capacity adjacency (single kernel) ------------
// g_cur is zero on entry (globals start zeroed; agg2 restores the invariant).
// Block 0 additionally zeroes the pooled output and counts.
__global__ void scatter_kernel(const int* __restrict__ src,
                               const int* __restrict__ dst,
                               float* __restrict__ out) {
    if (blockIdx.x == 0) {
        for (int t = threadIdx.x; t < N_GRAPHS * O2F; t += blockDim.x)
            out[t] = 0.0f;
        for (int t = threadIdx.x; t < N_GRAPHS; t += blockDim.x)
            g_cnt[t] = 0.0f;
    }
    int i = blockIdx.x * blockDim.x + threadIdx.x;
    if (i >= N_EDGES / 2) return;
    int j = i + N_EDGES / 2;
    int d0 = dst[i], d1 = dst[j];
    int s0 = src[i], s1 = src[j];
    int p0 = atomicAdd(&g_cur[d0], 1);
    int p1 = atomicAdd(&g_cur[d1], 1);
    if (p0 < CAP) g_esrc[d0 * CAP + p0] = s0;
    if (p1 < CAP) g_esrc[d1 * CAP + p1] = s1;
}

// ---------------- node GEMM + attention logits (NPTx4 register tiling) ------
// NPT nodes x 4 cols per thread; (OUT/4)*(NPB/NPT) must equal 256.
template <int IN, int OUT, int NPB, int NPT>
__global__ void gemm_attn_kernel(const float* __restrict__ H,
                                 const float* __restrict__ W,
                                 const float* __restrict__ al,
                                 const float* __restrict__ ar,
                                 float* __restrict__ Z,
                                 float* __restrict__ EL,
                                 float* __restrict__ ER) {
    constexpr int CG = OUT / 4;
    constexpr int NG = NPB / NPT;
    constexpr int NT = CG * NG;        // 256
    constexpr int KC = 32;
    constexpr int NKC = IN / KC;
    constexpr int KQ = KC / 4;
    constexpr int PITCH = NPB + 4;

    __shared__ float sx[KC * PITCH];
    __shared__ float sW[KC * OUT];

    int tid = threadIdx.x;
    int base = blockIdx.x * NPB;
    int ng = tid / CG, cg = tid % CG;
    int nn = ng * NPT;

    float4 acc[NPT];
#pragma unroll
    for (int n = 0; n < NPT; n++) acc[n] = make_float4(0.f, 0.f, 0.f, 0.f);

    for (int kc = 0; kc < NKC; kc++) {
        __syncthreads();
        for (int t = tid; t < KC * OUT / 4; t += NT)
            ((float4*)sW)[t] = ((const float4*)W)[kc * (KC * OUT / 4) + t];
        for (int t = tid; t < NPB * KQ; t += NT) {
            int node = t / KQ, kq = t % KQ;
            float4 v = make_float4(0.f, 0.f, 0.f, 0.f);
            if (base + node < N_NODES)
                v = ((const float4*)(H + (size_t)(base + node) * IN))[kc * KQ + kq];
            sx[(kq * 4 + 0) * PITCH + node] = v.x;
            sx[(kq * 4 + 1) * PITCH + node] = v.y;
            sx[(kq * 4 + 2) * PITCH + node] = v.z;
            sx[(kq * 4 + 3) * PITCH + node] = v.w;
        }
        __syncthreads();

#pragma unroll 8
        for (int k = 0; k < KC; k++) {
            float xs[NPT];
#pragma unroll
            for (int q = 0; q < NPT / 4; q++) {
                float4 xq = *(const float4*)(sx + k * PITCH + nn + q * 4);
                xs[q * 4 + 0] = xq.x;
                xs[q * 4 + 1] = xq.y;
                xs[q * 4 + 2] = xq.z;
                xs[q * 4 + 3] = xq.w;
            }
            float4 w = *(const float4*)(sW + k * OUT + cg * 4);
#pragma unroll
            for (int n = 0; n < NPT; n++) {
                acc[n].x += xs[n] * w.x;
                acc[n].y += xs[n] * w.y;
                acc[n].z += xs[n] * w.z;
                acc[n].w += xs[n] * w.w;
            }
        }
    }

    float4 av = ((const float4*)al)[cg];
    float4 rv = ((const float4*)ar)[cg];
#pragma unroll
    for (int n = 0; n < NPT; n++) {
        float l = acc[n].x * av.x + acc[n].y * av.y +
                  acc[n].z * av.z + acc[n].w * av.w;
        float r = acc[n].x * rv.x + acc[n].y * rv.y +
                  acc[n].z * rv.z + acc[n].w * rv.w;
#pragma unroll
        for (int off = CG / 2; off > 0; off >>= 1) {
            l += __shfl_xor_sync(0xffffffffu, l, off);
            r += __shfl_xor_sync(0xffffffffu, r, off);
        }
        int node = base + nn + n;
        if (node < N_NODES) {
            ((float4*)(Z + (size_t)node * OUT))[cg] = acc[n];
            if (cg == 0) { EL[node] = l; ER[node] = r; }
        }
    }
}

// ---------------- fused softmax + aggregation (max-free), warp per node -----
// The POOL (last) variant resets g_cur[wid] = 0 for the next graph replay.
template <int OUT, bool POOL>
__global__ void node_agg_kernel(const float* __restrict__ Z,
                                const float* __restrict__ b,
                                float* __restrict__ Hout,
                                const int* __restrict__ gid,
                                float* __restrict__ out) {
    constexpr int LPE = OUT / 4;
    constexpr int EPI = 32 / LPE;
    int wid  = (blockIdx.x * blockDim.x + threadIdx.x) >> 5;
    int lane = threadIdx.x & 31;
    if (wid >= N_NODES) return;

    int deg = min(g_cur[wid], CAP);
    const int* row = g_esrc + (size_t)wid * CAP;
    float erd = g_er[wid];
    int sub = lane / LPE;
    int fl  = lane % LPE;

    float s_lane = 0.f;
    float4 acc = make_float4(0.f, 0.f, 0.f, 0.f);

    for (int base = 0; base < deg; base += 32) {
        int t = base + lane;
        bool valid = t < deg;
        int sN = valid ? row[t] : 0;
        float a = 0.f;
        if (valid) {
            float v = g_el[sN] + erd;
            v = (v > 0.f) ? v : 0.2f * v;
            a = __expf(v);
        }
        s_lane += a;

        int cnt = min(32, deg - base);
        for (int j = 0; j < cnt; j += EPI) {
            int ei = j + sub;
            float alpha = __shfl_sync(0xffffffffu, a, ei);
            int   sn    = __shfl_sync(0xffffffffu, sN, ei);
            float4 zv = ((const float4*)(Z + (size_t)sn * OUT))[fl];
            acc.x += alpha * zv.x;
            acc.y += alpha * zv.y;
            acc.z += alpha * zv.z;
            acc.w += alpha * zv.w;
        }
    }

    float s = s_lane;
#pragma unroll
    for (int off = 16; off > 0; off >>= 1)
        s += __shfl_xor_sync(0xffffffffu, s, off);
#pragma unroll
    for (int off = 16; off >= LPE; off >>= 1) {
        acc.x += __shfl_xor_sync(0xffffffffu, acc.x, off);
        acc.y += __shfl_xor_sync(0xffffffffu, acc.y, off);
        acc.z += __shfl_xor_sync(0xffffffffu, acc.z, off);
        acc.w += __shfl_xor_sync(0xffffffffu, acc.w, off);
    }

    if (POOL && lane == 0) g_cur[wid] = 0;   // restore invariant for replay

    if (lane < LPE) {
        float inv_s = (deg > 0) ? 1.f / s : 0.f;
        float4 bq = ((const float4*)b)[fl];
        float4 h;
        h.x = acc.x * inv_s + bq.x;
        h.y = acc.y * inv_s + bq.y;
        h.z = acc.z * inv_s + bq.z;
        h.w = acc.w * inv_s + bq.w;
        h.x = (h.x > 0.f) ? h.x : 0.01f * h.x;
        h.y = (h.y > 0.f) ? h.y : 0.01f * h.y;
        h.z = (h.z > 0.f) ? h.z : 0.01f * h.z;
        h.w = (h.w > 0.f) ? h.w : 0.01f * h.w;
        if (POOL) {
            int g = gid[wid];
            atomicAdd(((float4*)(out + g * O2F)) + fl, h);
            if (lane == 0) atomicAdd(&g_cnt[g], 1.f);
        } else {
            ((float4*)(Hout + (size_t)wid * OUT))[fl] = h;
        }
    }
}

// ---------------- final divide ----------------------------------------------
__global__ void pool_div_kernel(float* __restrict__ out) {
    int i = blockIdx.x * blockDim.x + threadIdx.x;
    if (i >= N_GRAPHS * O2F) return;
    float c = g_cnt[i / O2F];
    out[i] /= fmaxf(c, 1.0f);
}

// ---------------- stream/event singletons (created once, outside capture) ---
static cudaStream_t g_s1;
static cudaEvent_t  g_evFork, g_evJoin;
static int g_res_init = []() {
    cudaStreamCreateWithFlags(&g_s1, cudaStreamNonBlocking);
    cudaEventCreateWithFlags(&g_evFork, cudaEventDisableTiming);
    cudaEventCreateWithFlags(&g_evJoin, cudaEventDisableTiming);
    return 0;
}();

// ---------------- host launch -------------------------------------------------
extern "C" void kernel_launch(void* const* d_in, const int* in_sizes, int n_in,
                              void* d_out, int out_size) {
    const float* x   = (const float*)d_in[0];
    const int*   src = (const int*)d_in[1];
    const int*   dst = (const int*)d_in[2];
    const int*   gid = (const int*)d_in[3];
    const float* W1  = (const float*)d_in[4];
    const float* al1 = (const float*)d_in[5];
    const float* ar1 = (const float*)d_in[6];
    const float* b1  = (const float*)d_in[7];
    const float* W2  = (const float*)d_in[8];
    const float* al2 = (const float*)d_in[9];
    const float* ar2 = (const float*)d_in[10];
    const float* b2  = (const float*)d_in[11];
    float* out = (float*)d_out;

    float *z1, *h1, *z2, *el, *er;
    cudaGetSymbolAddress((void**)&z1, g_z1);
    cudaGetSymbolAddress((void**)&h1, g_h1);
    cudaGetSymbolAddress((void**)&z2, g_z2);
    cudaGetSymbolAddress((void**)&el, g_el);
    cudaGetSymbolAddress((void**)&er, g_er);

    const int TB = 256;
    const int edge2_blocks = (N_EDGES / 2 + TB - 1) / TB;
    const int agg_blocks   = (N_NODES * 32) / TB;        // 6250

    // fork: adjacency build on side stream, gemm1 on main stream
    cudaEventRecord(g_evFork, 0);
    cudaStreamWaitEvent(g_s1, g_evFork, 0);

    scatter_kernel<<<edge2_blocks, TB, 0, g_s1>>>(src, dst, out);
    cudaEventRecord(g_evJoin, g_s1);

    // layer-1 GEMM: 128 nodes/block, 8 nodes/thread (proven config)
    gemm_attn_kernel<IN_FEATS, H1F, 128, 8>
        <<<(N_NODES + 127) / 128, 256>>>(x, W1, al1, ar1, z1, el, er);

    cudaStreamWaitEvent(0, g_evJoin, 0);

    node_agg_kernel<H1F, false><<<agg_blocks, TB>>>(z1, b1, h1, gid, out);

    // layer-2 GEMM: 128 nodes/block, 4 nodes/thread -> 391 blocks, high occ
    gemm_attn_kernel<H1F, O2F, 128, 4>
        <<<(N_NODES + 127) / 128, 256>>>(h1, W2, al2, ar2, z2, el, er);

    node_agg_kernel<O2F, true><<<agg_blocks, TB>>>(z2, b2, nullptr, gid, out);

    pool_div_kernel<<<(N_GRAPHS * O2F + TB - 1) / TB, TB>>>(out);
}